// round 13
// baseline (speedup 1.0000x reference)
#include <cuda_runtime.h>
#include <cuda_bf16.h>
#include <cstdint>

// Problem shape (fixed by the dataset)
#define T_TOK 8192
#define K_IN  4096
#define N_OUT 4096
#define GROUP 32

// Dequantized scratch (bf16 is exact for MXFP4 values)
__device__ __nv_bfloat16 g_xq[(size_t)T_TOK * K_IN];   // 64 MB
__device__ __nv_bfloat16 g_wq[(size_t)N_OUT * K_IN];   // 32 MB

// ---------------------------------------------------------------------------
// Kernel 1: Hadamard rotate + MXFP4 qdq. One thread per 32-elem group,
// FWHT fully in registers, 8x LDG.128 in, 4x STG.128 out.
// ---------------------------------------------------------------------------
#define XGRP ((long long)T_TOK * K_IN / GROUP)
#define TGRP (XGRP + (long long)N_OUT * K_IN / GROUP)

__global__ __launch_bounds__(256)
void rotate_quant_kernel(const float4* __restrict__ x4,
                         const float4* __restrict__ w4,
                         uint4* __restrict__ xq4,
                         uint4* __restrict__ wq4) {
    long long g = (long long)blockIdx.x * blockDim.x + threadIdx.x;
    if (g >= TGRP) return;

    const float4* src;
    uint4* dst;
    if (g < XGRP) { src = x4 + g * 8;          dst = xq4 + g * 4; }
    else          { src = w4 + (g - XGRP) * 8; dst = wq4 + (g - XGRP) * 4; }

    float v[32];
    #pragma unroll
    for (int i = 0; i < 8; i++) {
        float4 t = src[i];
        v[4 * i] = t.x; v[4 * i + 1] = t.y; v[4 * i + 2] = t.z; v[4 * i + 3] = t.w;
    }

    #pragma unroll
    for (int st = 1; st < 32; st <<= 1) {
        #pragma unroll
        for (int i = 0; i < 32; i++) {
            if (!(i & st)) {
                float a = v[i], b = v[i | st];
                v[i] = a + b; v[i | st] = a - b;
            }
        }
    }
    const float c = 0.17677669529663688f;   // 1/sqrt(32)
    float amax = 0.0f;
    #pragma unroll
    for (int i = 0; i < 32; i++) { v[i] *= c; amax = fmaxf(amax, fabsf(v[i])); }
    amax = fmaxf(amax, 1.1754943508222875e-38f);

    int e = (int)((__float_as_uint(amax) >> 23) & 0xFF) - 127 - 2;
    e = max(-127, min(127, e));
    const float scale  = ldexpf(1.0f, e);
    const float iscale = ldexpf(1.0f, -e);

    uint32_t wbuf[16];
    #pragma unroll
    for (int i = 0; i < 32; i += 2) {
        uint32_t pk = 0;
        #pragma unroll
        for (int r = 0; r < 2; r++) {
            float s = v[i + r] * iscale;
            float a = fminf(fabsf(s), 6.0f);
            float q;
            if (a > 2.5f)       q = (a > 5.0f)  ? 6.0f : ((a > 3.5f)  ? 4.0f : 3.0f);
            else if (a > 1.25f) q = (a > 1.75f) ? 2.0f : 1.5f;
            else                q = (a > 0.75f) ? 1.0f : ((a > 0.25f) ? 0.5f : 0.0f);
            float res = copysignf(q, s) * scale;
            pk |= (uint32_t)__bfloat16_as_ushort(__float2bfloat16(res)) << (16 * r);
        }
        wbuf[i >> 1] = pk;
    }
    #pragma unroll
    for (int i = 0; i < 4; i++)
        dst[i] = make_uint4(wbuf[4 * i], wbuf[4 * i + 1], wbuf[4 * i + 2], wbuf[4 * i + 3]);
}

// ---------------------------------------------------------------------------
// Kernel 2: bf16 GEMM  C[M,N] = A[M,K] @ B[N,K]^T + bias, fp32 accumulate.
// 64x128 CTA tile, 128 threads (4 warps, 2x2), warp tile 32x64,
// 4 CTAs per SM. BK=32 stages (80B rows), 3 smem slots, wait_group 1:
// stage t streams stage t+2 (3 chunks per k16 step), so every cp.async
// chunk gets a FULL stage of slack before the wait that consumes it.
// ---------------------------------------------------------------------------
#define BM 64
#define BN 128
#define BK 32
#define ROWB 80                         // 64B row + 16B pad (20-word stride:
                                        // 8 rows x 16B cover all 32 banks)
#define A_BYTES (BM * ROWB)             // 5120
#define B_BYTES (BN * ROWB)             // 10240
#define STG_B (A_BYTES + B_BYTES)       // 15360
#define MI_STEP (16 * ROWB)             // 1280: 16 rows in smem
#define CHNK_S (32 * ROWB)              // 2560: 32-row chunk in smem
#define CHNK_G (32 * K_IN * 2)          // 262144: 32-row chunk in gmem
#define SMEM_BYTES (3 * STG_B + 512)    // 46592  (x4 CTAs = 186KB)

__device__ __forceinline__ uint32_t smem_u32(const void* p) {
    uint32_t a;
    asm("{ .reg .u64 t; cvta.to.shared.u64 t, %1; cvt.u32.u64 %0, t; }"
        : "=r"(a) : "l"(p));
    return a;
}
#define LDSM4(r0, r1, r2, r3, addr)                                           \
    asm volatile("ldmatrix.sync.aligned.m8n8.x4.shared.b16 {%0,%1,%2,%3}, [%4];" \
                 : "=r"(r0), "=r"(r1), "=r"(r2), "=r"(r3) : "r"(addr))
#define MMA16816(c, a0, a1, a2, a3, b0, b1)                                   \
    asm volatile("mma.sync.aligned.m16n8k16.row.col.f32.bf16.bf16.f32 "       \
                 "{%0,%1,%2,%3},{%4,%5,%6,%7},{%8,%9},{%0,%1,%2,%3};"          \
                 : "+f"(c[0]), "+f"(c[1]), "+f"(c[2]), "+f"(c[3])              \
                 : "r"(a0), "r"(a1), "r"(a2), "r"(a3), "r"(b0), "r"(b1))
#define CPASYNC(dst, src)                                                     \
    asm volatile("cp.async.cg.shared.global [%0], [%1], 16;"                  \
                 :: "r"(dst), "l"(src))

__global__ __launch_bounds__(128, 4)
void gemm_bf16_kernel(const __nv_bfloat16* __restrict__ A,
                      const __nv_bfloat16* __restrict__ B,
                      const float* __restrict__ bias,
                      float* __restrict__ C) {
    extern __shared__ char smem[];
    const uint32_t sbase = smem_u32(smem);
    float* sBias = (float*)(smem + 3 * STG_B);

    const int tid = threadIdx.x;
    const int bm = blockIdx.y, bn = blockIdx.x;
    const int warp = tid >> 5, lane = tid & 31;
    const int wm = warp & 1;            // 0..1, 32 rows
    const int wn = warp >> 1;           // 0..1, 64 cols

    sBias[tid] = bias[bn * BN + tid];

    // --- cp.async addressing: row0 = tid/4 (0..31), 16B chunk cc = tid%4.
    // A chunk i covers rows row0 + i*32 (i=0..1); B chunk j rows row0+j*32
    // (j=0..3). 32-row gmem stride = 262144 bytes (immediate).
    const int row0 = tid >> 2, cc = tid & 3;
    const uint32_t dA0 = row0 * ROWB + cc * 16;
    const uint32_t dB0 = A_BYTES + dA0;
    const char* Ap = (const char*)(A + (size_t)(bm * BM + row0) * K_IN) + cc * 16;
    const char* Bp = (const char*)(B + (size_t)(bn * BN + row0) * K_IN) + cc * 16;

    auto load_full = [&](uint32_t slotOff) {
        const uint32_t base = sbase + slotOff;
        CPASYNC(base + dA0,           Ap);
        CPASYNC(base + dA0 + CHNK_S,  Ap + CHNK_G);
        #pragma unroll
        for (int j = 0; j < 4; j++)
            CPASYNC(base + dB0 + j * CHNK_S, Bp + (size_t)j * CHNK_G);
        asm volatile("cp.async.commit_group;");
        Ap += BK * 2; Bp += BK * 2;
    };

    // --- fragment base addresses (hoisted) ---
    const uint32_t aBase = sbase + (wm * 32 + (lane & 15)) * ROWB + ((lane >> 4) << 4);
    const uint32_t bBase = sbase + A_BYTES + (wn * 64 + (lane & 15)) * ROWB + ((lane >> 4) << 4);

    float acc[2][8][4];
    #pragma unroll
    for (int mi = 0; mi < 2; mi++)
        #pragma unroll
        for (int ni = 0; ni < 8; ni++)
            #pragma unroll
            for (int r = 0; r < 4; r++) acc[mi][ni][r] = 0.0f;

    // One BK=32 stage (2 k16 steps). If doLoad, stream stage t+2's chunks
    // into slot lOffC: 3 at ks=0 (A0,A1,B0), 3 at ks=1 (B1,B2,B3).
    auto compute_stage = [&](uint32_t cOffC, uint32_t lOffC, bool doLoad) {
        const uint32_t aOff = aBase + cOffC;
        const uint32_t bOff = bBase + cOffC;
        const uint32_t lbase = sbase + lOffC;

        uint32_t aF[2][2][4];        // [buf][mi][reg]
        uint32_t bF[2][4];           // [buf][reg]
        LDSM4(aF[0][0][0], aF[0][0][1], aF[0][0][2], aF[0][0][3], aOff);
        LDSM4(aF[0][1][0], aF[0][1][1], aF[0][1][2], aF[0][1][3], aOff + MI_STEP);
        LDSM4(bF[0][0], bF[0][1], bF[0][2], bF[0][3], bOff);

        #pragma unroll
        for (int ks = 0; ks < 2; ks++) {
            const int ab = ks;
            if (ks == 0) {           // prefetch A frags for ks=1
                LDSM4(aF[1][0][0], aF[1][0][1], aF[1][0][2], aF[1][0][3],
                      aOff + 32);
                LDSM4(aF[1][1][0], aF[1][1][1], aF[1][1][2], aF[1][1][3],
                      aOff + MI_STEP + 32);
            }
            if (doLoad) {
                if (ks == 0) {
                    CPASYNC(lbase + dA0,          Ap);
                    CPASYNC(lbase + dA0 + CHNK_S, Ap + CHNK_G);
                    CPASYNC(lbase + dB0,          Bp);
                } else {
                    CPASYNC(lbase + dB0 + 1 * CHNK_S, Bp + (size_t)1 * CHNK_G);
                    CPASYNC(lbase + dB0 + 2 * CHNK_S, Bp + (size_t)2 * CHNK_G);
                    CPASYNC(lbase + dB0 + 3 * CHNK_S, Bp + (size_t)3 * CHNK_G);
                }
            }
            #pragma unroll
            for (int p = 0; p < 4; p++) {
                const int bb = p & 1;
                if (p < 3)
                    LDSM4(bF[bb ^ 1][0], bF[bb ^ 1][1], bF[bb ^ 1][2], bF[bb ^ 1][3],
                          bOff + (p + 1) * MI_STEP + ks * 32);
                else if (ks == 0)
                    LDSM4(bF[bb ^ 1][0], bF[bb ^ 1][1], bF[bb ^ 1][2], bF[bb ^ 1][3],
                          bOff + 32);
                #pragma unroll
                for (int mi = 0; mi < 2; mi++) {
                    MMA16816(acc[mi][2 * p],     aF[ab][mi][0], aF[ab][mi][1],
                             aF[ab][mi][2], aF[ab][mi][3], bF[bb][0], bF[bb][2]);
                    MMA16816(acc[mi][2 * p + 1], aF[ab][mi][0], aF[ab][mi][1],
                             aF[ab][mi][2], aF[ab][mi][3], bF[bb][1], bF[bb][3]);
                }
            }
        }
    };

    // KT = 128 stages of BK=32; 3 slots, wait_group 1, lookahead 2.
    load_full(0 * STG_B);               // stage 0 -> slot 0
    load_full(1 * STG_B);               // stage 1 -> slot 1

    for (int t = 0; t < 126; t += 3) {
        // stage t   (slot 0), streams t+2 -> slot 2
        asm volatile("cp.async.wait_group 1;");
        __syncthreads();
        compute_stage(0 * STG_B, 2 * STG_B, true);
        asm volatile("cp.async.commit_group;");
        Ap += BK * 2; Bp += BK * 2;
        // stage t+1 (slot 1), streams t+3 -> slot 0
        asm volatile("cp.async.wait_group 1;");
        __syncthreads();
        compute_stage(1 * STG_B, 0 * STG_B, true);
        asm volatile("cp.async.commit_group;");
        Ap += BK * 2; Bp += BK * 2;
        // stage t+2 (slot 2), streams t+4 -> slot 1
        asm volatile("cp.async.wait_group 1;");
        __syncthreads();
        compute_stage(2 * STG_B, 1 * STG_B, t + 4 < 128);
        asm volatile("cp.async.commit_group;");
        Ap += BK * 2; Bp += BK * 2;
    }
    // stage 126 (slot 0)
    asm volatile("cp.async.wait_group 1;");
    __syncthreads();
    compute_stage(0 * STG_B, 0, false);
    // stage 127 (slot 1)
    asm volatile("cp.async.wait_group 0;");
    __syncthreads();
    compute_stage(1 * STG_B, 0, false);

    // Epilogue: bias (from smem) + fp32 stores
    const size_t rowbase = (size_t)bm * BM + wm * 32 + (lane >> 2);
    const int coll = wn * 64 + (lane & 3) * 2;
    float* Cb = C + (size_t)bn * BN + coll;
    #pragma unroll
    for (int ni = 0; ni < 8; ni++) {
        const float bb0 = sBias[coll + ni * 8];
        const float bb1 = sBias[coll + ni * 8 + 1];
        #pragma unroll
        for (int mi = 0; mi < 2; mi++) {
            const size_t r0 = rowbase + mi * 16;
            float2 v0 = make_float2(acc[mi][ni][0] + bb0, acc[mi][ni][1] + bb1);
            float2 v1 = make_float2(acc[mi][ni][2] + bb0, acc[mi][ni][3] + bb1);
            *(float2*)&Cb[r0 * N_OUT + ni * 8]       = v0;
            *(float2*)&Cb[(r0 + 8) * N_OUT + ni * 8] = v1;
        }
    }
}

// ---------------------------------------------------------------------------
extern "C" void kernel_launch(void* const* d_in, const int* in_sizes, int n_in,
                              void* d_out, int out_size) {
    const float* x    = (const float*)d_in[0];   // [T, K] fp32
    const float* w    = (const float*)d_in[1];   // [N, K] fp32
    const float* bias = (const float*)d_in[2];   // [N]    fp32
    float* out = (float*)d_out;                  // [T, N] fp32

    __nv_bfloat16 *xq, *wq;
    cudaGetSymbolAddress((void**)&xq, g_xq);
    cudaGetSymbolAddress((void**)&wq, g_wq);

    rotate_quant_kernel<<<(int)(TGRP / 256), 256>>>(
        (const float4*)x, (const float4*)w, (uint4*)xq, (uint4*)wq);

    cudaFuncSetAttribute(gemm_bf16_kernel,
                         cudaFuncAttributeMaxDynamicSharedMemorySize, SMEM_BYTES);
    dim3 grid(N_OUT / BN, T_TOK / BM);
    gemm_bf16_kernel<<<grid, 128, SMEM_BYTES>>>(xq, wq, bias, out);
}

// round 14
// speedup vs baseline: 1.0997x; 1.0997x over previous
#include <cuda_runtime.h>
#include <cuda_bf16.h>
#include <cstdint>

// Problem shape (fixed by the dataset)
#define T_TOK 8192
#define K_IN  4096
#define N_OUT 4096
#define GROUP 32

// Dequantized scratch (bf16 is exact for MXFP4 values)
__device__ __nv_bfloat16 g_xq[(size_t)T_TOK * K_IN];   // 64 MB
__device__ __nv_bfloat16 g_wq[(size_t)N_OUT * K_IN];   // 32 MB

// ---------------------------------------------------------------------------
// Kernel 1: Hadamard rotate + MXFP4 qdq. One thread per 32-elem group,
// FWHT fully in registers, 8x LDG.128 in, 4x STG.128 out.
// ---------------------------------------------------------------------------
#define XGRP ((long long)T_TOK * K_IN / GROUP)
#define TGRP (XGRP + (long long)N_OUT * K_IN / GROUP)

__global__ __launch_bounds__(256)
void rotate_quant_kernel(const float4* __restrict__ x4,
                         const float4* __restrict__ w4,
                         uint4* __restrict__ xq4,
                         uint4* __restrict__ wq4) {
    long long g = (long long)blockIdx.x * blockDim.x + threadIdx.x;
    if (g >= TGRP) return;

    const float4* src;
    uint4* dst;
    if (g < XGRP) { src = x4 + g * 8;          dst = xq4 + g * 4; }
    else          { src = w4 + (g - XGRP) * 8; dst = wq4 + (g - XGRP) * 4; }

    float v[32];
    #pragma unroll
    for (int i = 0; i < 8; i++) {
        float4 t = src[i];
        v[4 * i] = t.x; v[4 * i + 1] = t.y; v[4 * i + 2] = t.z; v[4 * i + 3] = t.w;
    }

    #pragma unroll
    for (int st = 1; st < 32; st <<= 1) {
        #pragma unroll
        for (int i = 0; i < 32; i++) {
            if (!(i & st)) {
                float a = v[i], b = v[i | st];
                v[i] = a + b; v[i | st] = a - b;
            }
        }
    }
    const float c = 0.17677669529663688f;   // 1/sqrt(32)
    float amax = 0.0f;
    #pragma unroll
    for (int i = 0; i < 32; i++) { v[i] *= c; amax = fmaxf(amax, fabsf(v[i])); }
    amax = fmaxf(amax, 1.1754943508222875e-38f);

    int e = (int)((__float_as_uint(amax) >> 23) & 0xFF) - 127 - 2;
    e = max(-127, min(127, e));
    const float scale  = ldexpf(1.0f, e);
    const float iscale = ldexpf(1.0f, -e);

    uint32_t wbuf[16];
    #pragma unroll
    for (int i = 0; i < 32; i += 2) {
        uint32_t pk = 0;
        #pragma unroll
        for (int r = 0; r < 2; r++) {
            float s = v[i + r] * iscale;
            float a = fminf(fabsf(s), 6.0f);
            float q;
            if (a > 2.5f)       q = (a > 5.0f)  ? 6.0f : ((a > 3.5f)  ? 4.0f : 3.0f);
            else if (a > 1.25f) q = (a > 1.75f) ? 2.0f : 1.5f;
            else                q = (a > 0.75f) ? 1.0f : ((a > 0.25f) ? 0.5f : 0.0f);
            float res = copysignf(q, s) * scale;
            pk |= (uint32_t)__bfloat16_as_ushort(__float2bfloat16(res)) << (16 * r);
        }
        wbuf[i >> 1] = pk;
    }
    #pragma unroll
    for (int i = 0; i < 4; i++)
        dst[i] = make_uint4(wbuf[4 * i], wbuf[4 * i + 1], wbuf[4 * i + 2], wbuf[4 * i + 3]);
}

// ---------------------------------------------------------------------------
// Kernel 2: bf16 GEMM  C[M,N] = A[M,K] @ B[N,K]^T + bias, fp32 accumulate.
// 64x128 CTA tile, 128 threads (4 warps, 2x2), warp tile 32x64,
// 4 CTAs per SM. BK=64, 2-stage cp.async, next-stage loads issued 4/4/4
// at ks=0,1,2 (R12 schedule). NEW: per-CTA K-phase rotation — each CTA
// starts its K loop at stage s0 = (bid*23)&63 so co-resident CTAs'
// stage-fill bursts de-synchronize at the LTS.
// ---------------------------------------------------------------------------
#define BM 64
#define BN 128
#define BK 64
#define LDE 72                          // bf16 per smem row (16B pad)
#define ROWB (LDE * 2)                  // 144 bytes
#define A_BYTES (BM * ROWB)             // 9216
#define B_BYTES (BN * ROWB)             // 18432
#define STG_B (A_BYTES + B_BYTES)       // 27648
#define MI_STEP (16 * ROWB)             // 2304
#define CHUNK_G (16 * K_IN * 2)         // 131072: 16-row stride in gmem bytes
#define KROW_B (K_IN * 2)               // 8192: one full K row in bytes
#define SMEM_BYTES (2 * STG_B + 512)    // 55808

__device__ __forceinline__ uint32_t smem_u32(const void* p) {
    uint32_t a;
    asm("{ .reg .u64 t; cvta.to.shared.u64 t, %1; cvt.u32.u64 %0, t; }"
        : "=r"(a) : "l"(p));
    return a;
}
#define LDSM4(r0, r1, r2, r3, addr)                                           \
    asm volatile("ldmatrix.sync.aligned.m8n8.x4.shared.b16 {%0,%1,%2,%3}, [%4];" \
                 : "=r"(r0), "=r"(r1), "=r"(r2), "=r"(r3) : "r"(addr))
#define MMA16816(c, a0, a1, a2, a3, b0, b1)                                   \
    asm volatile("mma.sync.aligned.m16n8k16.row.col.f32.bf16.bf16.f32 "       \
                 "{%0,%1,%2,%3},{%4,%5,%6,%7},{%8,%9},{%0,%1,%2,%3};"          \
                 : "+f"(c[0]), "+f"(c[1]), "+f"(c[2]), "+f"(c[3])              \
                 : "r"(a0), "r"(a1), "r"(a2), "r"(a3), "r"(b0), "r"(b1))
#define CPASYNC(dst, src)                                                     \
    asm volatile("cp.async.cg.shared.global [%0], [%1], 16;"                  \
                 :: "r"(dst), "l"(src))

__global__ __launch_bounds__(128, 4)
void gemm_bf16_kernel(const __nv_bfloat16* __restrict__ A,
                      const __nv_bfloat16* __restrict__ B,
                      const float* __restrict__ bias,
                      float* __restrict__ C) {
    extern __shared__ char smem[];
    const uint32_t sbase = smem_u32(smem);
    float* sBias = (float*)(smem + 2 * STG_B);

    const int tid = threadIdx.x;
    const int bm = blockIdx.y, bn = blockIdx.x;
    const int warp = tid >> 5, lane = tid & 31;
    const int wm = warp & 1;            // 0..1, 32 rows
    const int wn = warp >> 1;           // 0..1, 64 cols

    sBias[tid] = bias[bn * BN + tid];

    // --- cp.async base addressing: row0 = tid/8, 16B chunk cc = tid%8. ---
    const int row0 = tid >> 3, cc = tid & 7;
    const uint32_t dA0 = row0 * ROWB + cc * 16;
    const uint32_t dB0 = A_BYTES + dA0;

    // Per-CTA K-phase rotation: start at stage s0 (K offset s0*BK).
    const int bid = bn + (int)gridDim.x * bm;
    int ld = (bid * 23) & 63;           // next stage index to load
    const char* Ap = (const char*)(A + (size_t)(bm * BM + row0) * K_IN)
                     + cc * 16 + (size_t)ld * (BK * 2);
    const char* Bp = (const char*)(B + (size_t)(bn * BN + row0) * K_IN)
                     + cc * 16 + (size_t)ld * (BK * 2);

    auto bump = [&]() {                 // advance to next stage, wrap at 64
        Ap += BK * 2; Bp += BK * 2;
        if (++ld == 64) { ld = 0; Ap -= KROW_B; Bp -= KROW_B; }
    };

    auto load_full = [&](uint32_t slotOff) {
        const uint32_t base = sbase + slotOff;
        #pragma unroll
        for (int i = 0; i < 4; i++)
            CPASYNC(base + dA0 + i * MI_STEP, Ap + (size_t)i * CHUNK_G);
        #pragma unroll
        for (int j = 0; j < 8; j++)
            CPASYNC(base + dB0 + j * MI_STEP, Bp + (size_t)j * CHUNK_G);
        asm volatile("cp.async.commit_group;");
    };

    // --- fragment base addresses (hoisted) ---
    const uint32_t aBase = sbase + (wm * 32 + (lane & 15)) * ROWB + ((lane >> 4) << 4);
    const uint32_t bBase = sbase + A_BYTES + (wn * 64 + (lane & 15)) * ROWB + ((lane >> 4) << 4);

    float acc[2][8][4];
    #pragma unroll
    for (int mi = 0; mi < 2; mi++)
        #pragma unroll
        for (int ni = 0; ni < 8; ni++)
            #pragma unroll
            for (int r = 0; r < 4; r++) acc[mi][ni][r] = 0.0f;

    // Compute one stage; issue next stage's 12 chunks 4/4/4 at ks=0,1,2.
    auto compute_stage = [&](uint32_t cOffC, uint32_t lOffC, bool doLoad) {
        const uint32_t aOff = aBase + cOffC;
        const uint32_t bOff = bBase + cOffC;
        const uint32_t lbase = sbase + lOffC;

        uint32_t aF[2][2][4];        // [buf][mi][reg]
        uint32_t bF[2][4];           // [buf][reg]
        LDSM4(aF[0][0][0], aF[0][0][1], aF[0][0][2], aF[0][0][3], aOff);
        LDSM4(aF[0][1][0], aF[0][1][1], aF[0][1][2], aF[0][1][3], aOff + MI_STEP);
        LDSM4(bF[0][0], bF[0][1], bF[0][2], bF[0][3], bOff);

        #pragma unroll
        for (int ks = 0; ks < 4; ks++) {
            const int ab = ks & 1;
            if (ks < 3) {            // prefetch A frags for ks+1
                LDSM4(aF[ab ^ 1][0][0], aF[ab ^ 1][0][1],
                      aF[ab ^ 1][0][2], aF[ab ^ 1][0][3],
                      aOff + (ks + 1) * 32);
                LDSM4(aF[ab ^ 1][1][0], aF[ab ^ 1][1][1],
                      aF[ab ^ 1][1][2], aF[ab ^ 1][1][3],
                      aOff + MI_STEP + (ks + 1) * 32);
            }
            if (doLoad) {
                if (ks == 0) {
                    CPASYNC(lbase + dA0 + 0 * MI_STEP, Ap + (size_t)0 * CHUNK_G);
                    CPASYNC(lbase + dA0 + 1 * MI_STEP, Ap + (size_t)1 * CHUNK_G);
                    CPASYNC(lbase + dB0 + 0 * MI_STEP, Bp + (size_t)0 * CHUNK_G);
                    CPASYNC(lbase + dB0 + 1 * MI_STEP, Bp + (size_t)1 * CHUNK_G);
                } else if (ks == 1) {
                    CPASYNC(lbase + dA0 + 2 * MI_STEP, Ap + (size_t)2 * CHUNK_G);
                    CPASYNC(lbase + dA0 + 3 * MI_STEP, Ap + (size_t)3 * CHUNK_G);
                    CPASYNC(lbase + dB0 + 2 * MI_STEP, Bp + (size_t)2 * CHUNK_G);
                    CPASYNC(lbase + dB0 + 3 * MI_STEP, Bp + (size_t)3 * CHUNK_G);
                } else if (ks == 2) {
                    CPASYNC(lbase + dB0 + 4 * MI_STEP, Bp + (size_t)4 * CHUNK_G);
                    CPASYNC(lbase + dB0 + 5 * MI_STEP, Bp + (size_t)5 * CHUNK_G);
                    CPASYNC(lbase + dB0 + 6 * MI_STEP, Bp + (size_t)6 * CHUNK_G);
                    CPASYNC(lbase + dB0 + 7 * MI_STEP, Bp + (size_t)7 * CHUNK_G);
                }
            }
            #pragma unroll
            for (int p = 0; p < 4; p++) {
                const int bb = p & 1;
                if (p < 3)
                    LDSM4(bF[bb ^ 1][0], bF[bb ^ 1][1], bF[bb ^ 1][2], bF[bb ^ 1][3],
                          bOff + (p + 1) * MI_STEP + ks * 32);
                else if (ks < 3)
                    LDSM4(bF[bb ^ 1][0], bF[bb ^ 1][1], bF[bb ^ 1][2], bF[bb ^ 1][3],
                          bOff + (ks + 1) * 32);
                #pragma unroll
                for (int mi = 0; mi < 2; mi++) {
                    MMA16816(acc[mi][2 * p],     aF[ab][mi][0], aF[ab][mi][1],
                             aF[ab][mi][2], aF[ab][mi][3], bF[bb][0], bF[bb][2]);
                    MMA16816(acc[mi][2 * p + 1], aF[ab][mi][0], aF[ab][mi][1],
                             aF[ab][mi][2], aF[ab][mi][3], bF[bb][1], bF[bb][3]);
                }
            }
        }
    };

    // 64 stages starting at s0 (wrapping), 2 smem slots, lookahead 1.
    load_full(0);
    bump();                            // Ap/Bp -> stage s0+1

    for (int kt = 0; kt < 64; kt += 2) {
        // consumes slot 0, streams next stage into slot 1
        asm volatile("cp.async.wait_group 0;");
        __syncthreads();
        compute_stage(0 * STG_B, 1 * STG_B, true);
        asm volatile("cp.async.commit_group;");
        bump();
        // consumes slot 1, streams next stage into slot 0
        asm volatile("cp.async.wait_group 0;");
        __syncthreads();
        compute_stage(1 * STG_B, 0 * STG_B, kt + 2 < 64);
        asm volatile("cp.async.commit_group;");
        bump();
    }

    // Epilogue: bias (from smem) + fp32 stores
    const size_t rowbase = (size_t)bm * BM + wm * 32 + (lane >> 2);
    const int coll = wn * 64 + (lane & 3) * 2;
    float* Cb = C + (size_t)bn * BN + coll;
    #pragma unroll
    for (int ni = 0; ni < 8; ni++) {
        const float bb0 = sBias[coll + ni * 8];
        const float bb1 = sBias[coll + ni * 8 + 1];
        #pragma unroll
        for (int mi = 0; mi < 2; mi++) {
            const size_t r0 = rowbase + mi * 16;
            float2 v0 = make_float2(acc[mi][ni][0] + bb0, acc[mi][ni][1] + bb1);
            float2 v1 = make_float2(acc[mi][ni][2] + bb0, acc[mi][ni][3] + bb1);
            *(float2*)&Cb[r0 * N_OUT + ni * 8]       = v0;
            *(float2*)&Cb[(r0 + 8) * N_OUT + ni * 8] = v1;
        }
    }
}

// ---------------------------------------------------------------------------
extern "C" void kernel_launch(void* const* d_in, const int* in_sizes, int n_in,
                              void* d_out, int out_size) {
    const float* x    = (const float*)d_in[0];   // [T, K] fp32
    const float* w    = (const float*)d_in[1];   // [N, K] fp32
    const float* bias = (const float*)d_in[2];   // [N]    fp32
    float* out = (float*)d_out;                  // [T, N] fp32

    __nv_bfloat16 *xq, *wq;
    cudaGetSymbolAddress((void**)&xq, g_xq);
    cudaGetSymbolAddress((void**)&wq, g_wq);

    rotate_quant_kernel<<<(int)(TGRP / 256), 256>>>(
        (const float4*)x, (const float4*)w, (uint4*)xq, (uint4*)wq);

    cudaFuncSetAttribute(gemm_bf16_kernel,
                         cudaFuncAttributeMaxDynamicSharedMemorySize, SMEM_BYTES);
    dim3 grid(N_OUT / BN, T_TOK / BM);
    gemm_bf16_kernel<<<grid, 128, SMEM_BYTES>>>(xq, wq, bias, out);
}

// round 15
// speedup vs baseline: 1.1012x; 1.0013x over previous
#include <cuda_runtime.h>
#include <cuda_bf16.h>
#include <cstdint>

// Problem shape (fixed by the dataset)
#define T_TOK 8192
#define K_IN  4096
#define N_OUT 4096
#define GROUP 32

// Dequantized scratch (bf16 is exact for MXFP4 values)
__device__ __nv_bfloat16 g_xq[(size_t)T_TOK * K_IN];   // 64 MB
__device__ __nv_bfloat16 g_wq[(size_t)N_OUT * K_IN];   // 32 MB

// ---------------------------------------------------------------------------
// Kernel 1: Hadamard rotate + MXFP4 qdq. One thread per 32-elem group,
// FWHT fully in registers, 8x LDG.128.CS in (x/w are read-once: evict-first
// so they don't evict the xq/wq lines the GEMM is about to re-read),
// 4x STG.128 out.
// ---------------------------------------------------------------------------
#define XGRP ((long long)T_TOK * K_IN / GROUP)
#define TGRP (XGRP + (long long)N_OUT * K_IN / GROUP)

__global__ __launch_bounds__(256)
void rotate_quant_kernel(const float4* __restrict__ x4,
                         const float4* __restrict__ w4,
                         uint4* __restrict__ xq4,
                         uint4* __restrict__ wq4) {
    long long g = (long long)blockIdx.x * blockDim.x + threadIdx.x;
    if (g >= TGRP) return;

    const float4* src;
    uint4* dst;
    if (g < XGRP) { src = x4 + g * 8;          dst = xq4 + g * 4; }
    else          { src = w4 + (g - XGRP) * 8; dst = wq4 + (g - XGRP) * 4; }

    float v[32];
    #pragma unroll
    for (int i = 0; i < 8; i++) {
        float4 t = __ldcs(&src[i]);     // streaming: evict-first in L2
        v[4 * i] = t.x; v[4 * i + 1] = t.y; v[4 * i + 2] = t.z; v[4 * i + 3] = t.w;
    }

    #pragma unroll
    for (int st = 1; st < 32; st <<= 1) {
        #pragma unroll
        for (int i = 0; i < 32; i++) {
            if (!(i & st)) {
                float a = v[i], b = v[i | st];
                v[i] = a + b; v[i | st] = a - b;
            }
        }
    }
    const float c = 0.17677669529663688f;   // 1/sqrt(32)
    float amax = 0.0f;
    #pragma unroll
    for (int i = 0; i < 32; i++) { v[i] *= c; amax = fmaxf(amax, fabsf(v[i])); }
    amax = fmaxf(amax, 1.1754943508222875e-38f);

    int e = (int)((__float_as_uint(amax) >> 23) & 0xFF) - 127 - 2;
    e = max(-127, min(127, e));
    const float scale  = ldexpf(1.0f, e);
    const float iscale = ldexpf(1.0f, -e);

    uint32_t wbuf[16];
    #pragma unroll
    for (int i = 0; i < 32; i += 2) {
        uint32_t pk = 0;
        #pragma unroll
        for (int r = 0; r < 2; r++) {
            float s = v[i + r] * iscale;
            float a = fminf(fabsf(s), 6.0f);
            float q;
            if (a > 2.5f)       q = (a > 5.0f)  ? 6.0f : ((a > 3.5f)  ? 4.0f : 3.0f);
            else if (a > 1.25f) q = (a > 1.75f) ? 2.0f : 1.5f;
            else                q = (a > 0.75f) ? 1.0f : ((a > 0.25f) ? 0.5f : 0.0f);
            float res = copysignf(q, s) * scale;
            pk |= (uint32_t)__bfloat16_as_ushort(__float2bfloat16(res)) << (16 * r);
        }
        wbuf[i >> 1] = pk;
    }
    #pragma unroll
    for (int i = 0; i < 4; i++)
        dst[i] = make_uint4(wbuf[4 * i], wbuf[4 * i + 1], wbuf[4 * i + 2], wbuf[4 * i + 3]);
}

// ---------------------------------------------------------------------------
// Kernel 2: bf16 GEMM  C[M,N] = A[M,K] @ B[N,K]^T + bias, fp32 accumulate.
// 64x128 CTA tile, 128 threads (4 warps, 2x2), warp tile 32x64,
// 4 CTAs per SM. BK=64, 2-stage cp.async, next-stage loads issued 4/4/4
// at ks=0,1,2. Per-CTA K-phase rotation: each CTA starts its K loop at
// stage s0 = (bid*23)&63 so co-resident CTAs' stage-fill bursts
// de-synchronize at the LTS.  (UNCHANGED from round 14 — protected win.)
// ---------------------------------------------------------------------------
#define BM 64
#define BN 128
#define BK 64
#define LDE 72                          // bf16 per smem row (16B pad)
#define ROWB (LDE * 2)                  // 144 bytes
#define A_BYTES (BM * ROWB)             // 9216
#define B_BYTES (BN * ROWB)             // 18432
#define STG_B (A_BYTES + B_BYTES)       // 27648
#define MI_STEP (16 * ROWB)             // 2304
#define CHUNK_G (16 * K_IN * 2)         // 131072: 16-row stride in gmem bytes
#define KROW_B (K_IN * 2)               // 8192: one full K row in bytes
#define SMEM_BYTES (2 * STG_B + 512)    // 55808

__device__ __forceinline__ uint32_t smem_u32(const void* p) {
    uint32_t a;
    asm("{ .reg .u64 t; cvta.to.shared.u64 t, %1; cvt.u32.u64 %0, t; }"
        : "=r"(a) : "l"(p));
    return a;
}
#define LDSM4(r0, r1, r2, r3, addr)                                           \
    asm volatile("ldmatrix.sync.aligned.m8n8.x4.shared.b16 {%0,%1,%2,%3}, [%4];" \
                 : "=r"(r0), "=r"(r1), "=r"(r2), "=r"(r3) : "r"(addr))
#define MMA16816(c, a0, a1, a2, a3, b0, b1)                                   \
    asm volatile("mma.sync.aligned.m16n8k16.row.col.f32.bf16.bf16.f32 "       \
                 "{%0,%1,%2,%3},{%4,%5,%6,%7},{%8,%9},{%0,%1,%2,%3};"          \
                 : "+f"(c[0]), "+f"(c[1]), "+f"(c[2]), "+f"(c[3])              \
                 : "r"(a0), "r"(a1), "r"(a2), "r"(a3), "r"(b0), "r"(b1))
#define CPASYNC(dst, src)                                                     \
    asm volatile("cp.async.cg.shared.global [%0], [%1], 16;"                  \
                 :: "r"(dst), "l"(src))

__global__ __launch_bounds__(128, 4)
void gemm_bf16_kernel(const __nv_bfloat16* __restrict__ A,
                      const __nv_bfloat16* __restrict__ B,
                      const float* __restrict__ bias,
                      float* __restrict__ C) {
    extern __shared__ char smem[];
    const uint32_t sbase = smem_u32(smem);
    float* sBias = (float*)(smem + 2 * STG_B);

    const int tid = threadIdx.x;
    const int bm = blockIdx.y, bn = blockIdx.x;
    const int warp = tid >> 5, lane = tid & 31;
    const int wm = warp & 1;            // 0..1, 32 rows
    const int wn = warp >> 1;           // 0..1, 64 cols

    sBias[tid] = bias[bn * BN + tid];

    // --- cp.async base addressing: row0 = tid/8, 16B chunk cc = tid%8. ---
    const int row0 = tid >> 3, cc = tid & 7;
    const uint32_t dA0 = row0 * ROWB + cc * 16;
    const uint32_t dB0 = A_BYTES + dA0;

    // Per-CTA K-phase rotation: start at stage s0 (K offset s0*BK).
    const int bid = bn + (int)gridDim.x * bm;
    int ld = (bid * 23) & 63;           // next stage index to load
    const char* Ap = (const char*)(A + (size_t)(bm * BM + row0) * K_IN)
                     + cc * 16 + (size_t)ld * (BK * 2);
    const char* Bp = (const char*)(B + (size_t)(bn * BN + row0) * K_IN)
                     + cc * 16 + (size_t)ld * (BK * 2);

    auto bump = [&]() {                 // advance to next stage, wrap at 64
        Ap += BK * 2; Bp += BK * 2;
        if (++ld == 64) { ld = 0; Ap -= KROW_B; Bp -= KROW_B; }
    };

    auto load_full = [&](uint32_t slotOff) {
        const uint32_t base = sbase + slotOff;
        #pragma unroll
        for (int i = 0; i < 4; i++)
            CPASYNC(base + dA0 + i * MI_STEP, Ap + (size_t)i * CHUNK_G);
        #pragma unroll
        for (int j = 0; j < 8; j++)
            CPASYNC(base + dB0 + j * MI_STEP, Bp + (size_t)j * CHUNK_G);
        asm volatile("cp.async.commit_group;");
    };

    // --- fragment base addresses (hoisted) ---
    const uint32_t aBase = sbase + (wm * 32 + (lane & 15)) * ROWB + ((lane >> 4) << 4);
    const uint32_t bBase = sbase + A_BYTES + (wn * 64 + (lane & 15)) * ROWB + ((lane >> 4) << 4);

    float acc[2][8][4];
    #pragma unroll
    for (int mi = 0; mi < 2; mi++)
        #pragma unroll
        for (int ni = 0; ni < 8; ni++)
            #pragma unroll
            for (int r = 0; r < 4; r++) acc[mi][ni][r] = 0.0f;

    // Compute one stage; issue next stage's 12 chunks 4/4/4 at ks=0,1,2.
    auto compute_stage = [&](uint32_t cOffC, uint32_t lOffC, bool doLoad) {
        const uint32_t aOff = aBase + cOffC;
        const uint32_t bOff = bBase + cOffC;
        const uint32_t lbase = sbase + lOffC;

        uint32_t aF[2][2][4];        // [buf][mi][reg]
        uint32_t bF[2][4];           // [buf][reg]
        LDSM4(aF[0][0][0], aF[0][0][1], aF[0][0][2], aF[0][0][3], aOff);
        LDSM4(aF[0][1][0], aF[0][1][1], aF[0][1][2], aF[0][1][3], aOff + MI_STEP);
        LDSM4(bF[0][0], bF[0][1], bF[0][2], bF[0][3], bOff);

        #pragma unroll
        for (int ks = 0; ks < 4; ks++) {
            const int ab = ks & 1;
            if (ks < 3) {            // prefetch A frags for ks+1
                LDSM4(aF[ab ^ 1][0][0], aF[ab ^ 1][0][1],
                      aF[ab ^ 1][0][2], aF[ab ^ 1][0][3],
                      aOff + (ks + 1) * 32);
                LDSM4(aF[ab ^ 1][1][0], aF[ab ^ 1][1][1],
                      aF[ab ^ 1][1][2], aF[ab ^ 1][1][3],
                      aOff + MI_STEP + (ks + 1) * 32);
            }
            if (doLoad) {
                if (ks == 0) {
                    CPASYNC(lbase + dA0 + 0 * MI_STEP, Ap + (size_t)0 * CHUNK_G);
                    CPASYNC(lbase + dA0 + 1 * MI_STEP, Ap + (size_t)1 * CHUNK_G);
                    CPASYNC(lbase + dB0 + 0 * MI_STEP, Bp + (size_t)0 * CHUNK_G);
                    CPASYNC(lbase + dB0 + 1 * MI_STEP, Bp + (size_t)1 * CHUNK_G);
                } else if (ks == 1) {
                    CPASYNC(lbase + dA0 + 2 * MI_STEP, Ap + (size_t)2 * CHUNK_G);
                    CPASYNC(lbase + dA0 + 3 * MI_STEP, Ap + (size_t)3 * CHUNK_G);
                    CPASYNC(lbase + dB0 + 2 * MI_STEP, Bp + (size_t)2 * CHUNK_G);
                    CPASYNC(lbase + dB0 + 3 * MI_STEP, Bp + (size_t)3 * CHUNK_G);
                } else if (ks == 2) {
                    CPASYNC(lbase + dB0 + 4 * MI_STEP, Bp + (size_t)4 * CHUNK_G);
                    CPASYNC(lbase + dB0 + 5 * MI_STEP, Bp + (size_t)5 * CHUNK_G);
                    CPASYNC(lbase + dB0 + 6 * MI_STEP, Bp + (size_t)6 * CHUNK_G);
                    CPASYNC(lbase + dB0 + 7 * MI_STEP, Bp + (size_t)7 * CHUNK_G);
                }
            }
            #pragma unroll
            for (int p = 0; p < 4; p++) {
                const int bb = p & 1;
                if (p < 3)
                    LDSM4(bF[bb ^ 1][0], bF[bb ^ 1][1], bF[bb ^ 1][2], bF[bb ^ 1][3],
                          bOff + (p + 1) * MI_STEP + ks * 32);
                else if (ks < 3)
                    LDSM4(bF[bb ^ 1][0], bF[bb ^ 1][1], bF[bb ^ 1][2], bF[bb ^ 1][3],
                          bOff + (ks + 1) * 32);
                #pragma unroll
                for (int mi = 0; mi < 2; mi++) {
                    MMA16816(acc[mi][2 * p],     aF[ab][mi][0], aF[ab][mi][1],
                             aF[ab][mi][2], aF[ab][mi][3], bF[bb][0], bF[bb][2]);
                    MMA16816(acc[mi][2 * p + 1], aF[ab][mi][0], aF[ab][mi][1],
                             aF[ab][mi][2], aF[ab][mi][3], bF[bb][1], bF[bb][3]);
                }
            }
        }
    };

    // 64 stages starting at s0 (wrapping), 2 smem slots, lookahead 1.
    load_full(0);
    bump();                            // Ap/Bp -> stage s0+1

    for (int kt = 0; kt < 64; kt += 2) {
        // consumes slot 0, streams next stage into slot 1
        asm volatile("cp.async.wait_group 0;");
        __syncthreads();
        compute_stage(0 * STG_B, 1 * STG_B, true);
        asm volatile("cp.async.commit_group;");
        bump();
        // consumes slot 1, streams next stage into slot 0
        asm volatile("cp.async.wait_group 0;");
        __syncthreads();
        compute_stage(1 * STG_B, 0 * STG_B, kt + 2 < 64);
        asm volatile("cp.async.commit_group;");
        bump();
    }

    // Epilogue: bias (from smem) + fp32 stores
    const size_t rowbase = (size_t)bm * BM + wm * 32 + (lane >> 2);
    const int coll = wn * 64 + (lane & 3) * 2;
    float* Cb = C + (size_t)bn * BN + coll;
    #pragma unroll
    for (int ni = 0; ni < 8; ni++) {
        const float bb0 = sBias[coll + ni * 8];
        const float bb1 = sBias[coll + ni * 8 + 1];
        #pragma unroll
        for (int mi = 0; mi < 2; mi++) {
            const size_t r0 = rowbase + mi * 16;
            float2 v0 = make_float2(acc[mi][ni][0] + bb0, acc[mi][ni][1] + bb1);
            float2 v1 = make_float2(acc[mi][ni][2] + bb0, acc[mi][ni][3] + bb1);
            *(float2*)&Cb[r0 * N_OUT + ni * 8]       = v0;
            *(float2*)&Cb[(r0 + 8) * N_OUT + ni * 8] = v1;
        }
    }
}

// ---------------------------------------------------------------------------
extern "C" void kernel_launch(void* const* d_in, const int* in_sizes, int n_in,
                              void* d_out, int out_size) {
    const float* x    = (const float*)d_in[0];   // [T, K] fp32
    const float* w    = (const float*)d_in[1];   // [N, K] fp32
    const float* bias = (const float*)d_in[2];   // [N]    fp32
    float* out = (float*)d_out;                  // [T, N] fp32

    __nv_bfloat16 *xq, *wq;
    cudaGetSymbolAddress((void**)&xq, g_xq);
    cudaGetSymbolAddress((void**)&wq, g_wq);

    rotate_quant_kernel<<<(int)(TGRP / 256), 256>>>(
        (const float4*)x, (const float4*)w, (uint4*)xq, (uint4*)wq);

    cudaFuncSetAttribute(gemm_bf16_kernel,
                         cudaFuncAttributeMaxDynamicSharedMemorySize, SMEM_BYTES);
    dim3 grid(N_OUT / BN, T_TOK / BM);
    gemm_bf16_kernel<<<grid, 128, SMEM_BYTES>>>(xq, wq, bias, out);
}